// round 1
// baseline (speedup 1.0000x reference)
#include <cuda_runtime.h>

// HardLabel: out[n,c,h,w] = 1.0 if (c == gt(n,h,w)) and cond(n,h,w) else 0.0
//   gt   = channel where one-hot label == 1
//   cond = has_label && (prob[gt] < 0.9 || rand < 0.9)
// Exploits: label IS the one-hot -> write pass needs only gt index.
//           rand < thr short-circuits the prob gather (90% of pixels).

static constexpr int   kN  = 8;
static constexpr int   kC  = 22;
static constexpr int   kH  = 480;
static constexpr int   kW  = 640;
static constexpr int   kHW = kH * kW;          // 307200, divisible by 4
static constexpr float kThr = 0.9f;

__global__ __launch_bounds__(256)
void hardlabel_kernel(const float* __restrict__ prob,
                      const float* __restrict__ label,
                      const float* __restrict__ rnd,
                      float* __restrict__ out)
{
    const int g = blockIdx.x * blockDim.x + threadIdx.x;   // float4 group id
    const int total_groups = kN * kHW / 4;                 // 614400
    if (g >= total_groups) return;

    const int p   = g << 2;                // first pixel of this group
    const int n   = p / kHW;
    const int pix = p - n * kHW;           // pixel offset within image
    const int base = n * kC * kHW + pix;   // label/prob/out channel-0 offset

    // ---- pass 1: scan label channels, find gt per lane ----
    int gt0 = -1, gt1 = -1, gt2 = -1, gt3 = -1;
#pragma unroll
    for (int c = 0; c < kC; ++c) {
        const float4 l = *reinterpret_cast<const float4*>(label + base + c * kHW);
        if (gt0 < 0 && l.x > 0.0f) gt0 = c;
        if (gt1 < 0 && l.y > 0.0f) gt1 = c;
        if (gt2 < 0 && l.z > 0.0f) gt2 = c;
        if (gt3 < 0 && l.w > 0.0f) gt3 = c;
    }

    // ---- cond: rand short-circuit; gather prob only when needed ----
    const float4 r = *reinterpret_cast<const float4*>(rnd + p);

    bool cond0, cond1, cond2, cond3;
    if (gt0 < 0)            cond0 = false;
    else if (r.x < kThr)    cond0 = true;
    else                    cond0 = prob[base + gt0 * kHW + 0] < kThr;

    if (gt1 < 0)            cond1 = false;
    else if (r.y < kThr)    cond1 = true;
    else                    cond1 = prob[base + gt1 * kHW + 1] < kThr;

    if (gt2 < 0)            cond2 = false;
    else if (r.z < kThr)    cond2 = true;
    else                    cond2 = prob[base + gt2 * kHW + 2] < kThr;

    if (gt3 < 0)            cond3 = false;
    else if (r.w < kThr)    cond3 = true;
    else                    cond3 = prob[base + gt3 * kHW + 3] < kThr;

    // selected channel (-1 => write all zeros for that lane)
    const int s0 = cond0 ? gt0 : -1;
    const int s1 = cond1 ? gt1 : -1;
    const int s2 = cond2 ? gt2 : -1;
    const int s3 = cond3 ? gt3 : -1;

    // ---- pass 2: write one-hot output (no label re-read) ----
#pragma unroll
    for (int c = 0; c < kC; ++c) {
        float4 o;
        o.x = (c == s0) ? 1.0f : 0.0f;
        o.y = (c == s1) ? 1.0f : 0.0f;
        o.z = (c == s2) ? 1.0f : 0.0f;
        o.w = (c == s3) ? 1.0f : 0.0f;
        *reinterpret_cast<float4*>(out + base + c * kHW) = o;
    }
}

extern "C" void kernel_launch(void* const* d_in, const int* in_sizes, int n_in,
                              void* d_out, int out_size)
{
    const float* prob  = (const float*)d_in[0];
    const float* label = (const float*)d_in[1];
    const float* rnd   = (const float*)d_in[2];
    float* out = (float*)d_out;

    const int total_groups = kN * kHW / 4;   // 614400
    const int threads = 256;
    const int blocks  = (total_groups + threads - 1) / threads;  // 2400
    hardlabel_kernel<<<blocks, threads>>>(prob, label, rnd, out);
}